// round 11
// baseline (speedup 1.0000x reference)
#include <cuda_runtime.h>
#include <cuda_bf16.h>
#include <cstdint>

// ---------------- problem constants ----------------
#define BATCH   128
#define G_TOT   10000
#define KW      20
#define LAT     2000
#define KDIM    30000      // G*C
#define INLEN   200000
#define NPAD    2048
#define SPLIT_LEN 1216     // FC1 split-K length (19 blocks of 64)
#define KSPLIT  25         // last split = 816
#define NBLK_H  469        // ceil(30000/64)
#define NBLK_Z  32         // ceil(2000/64)

// Per 64-k block: [128 m][64 k] bf16, SW128 swizzled rows; hi 16KB then lo 16KB.
#define ABLK_BYTES 32768

// ---------------- device scratch (static, no allocation) ----------------
__device__ __align__(16) unsigned char g_hA[(size_t)NBLK_H * ABLK_BYTES];
__device__ __align__(16) unsigned char g_zA[(size_t)NBLK_Z * ABLK_BYTES];
__device__ float g_zpart[(size_t)KSPLIT * NPAD * 128];
__device__ float g_dT[(size_t)KDIM * 128];

// ---------------- helpers ----------------
__device__ __forceinline__ uint32_t smem_u32(const void* p) {
    uint32_t a;
    asm("{ .reg .u64 t; cvta.to.shared.u64 t, %1; cvt.u32.u64 %0, t; }" : "=r"(a) : "l"(p));
    return a;
}
__device__ __forceinline__ uint32_t swz128(uint32_t off) { return off ^ ((off >> 3) & 0x70); }
__device__ __forceinline__ float leaky(float v) { return v >= 0.0f ? v : 0.1f * v; }

// pack two fp32 -> bf16x2 (lo half = a, hi half = b)
__device__ __forceinline__ uint32_t bf2pack(float a, float b) {
    uint32_t r;
    asm("cvt.rn.bf16x2.f32 %0, %1, %2;" : "=r"(r) : "f"(b), "f"(a));
    return r;
}

__device__ __forceinline__ void ldsm4(uint32_t* r, uint32_t addr) {
    asm volatile("ldmatrix.sync.aligned.m8n8.x4.shared.b16 {%0,%1,%2,%3}, [%4];"
        : "=r"(r[0]), "=r"(r[1]), "=r"(r[2]), "=r"(r[3]) : "r"(addr));
}

__device__ __forceinline__ void mma16816(float* c, const uint32_t* a, uint32_t b0, uint32_t b1) {
    asm volatile("mma.sync.aligned.m16n8k16.row.col.f32.bf16.bf16.f32 "
        "{%0,%1,%2,%3}, {%4,%5,%6,%7}, {%8,%9}, {%0,%1,%2,%3};"
        : "+f"(c[0]), "+f"(c[1]), "+f"(c[2]), "+f"(c[3])
        : "r"(a[0]), "r"(a[1]), "r"(a[2]), "r"(a[3]), "r"(b0), "r"(b1));
}

__device__ __forceinline__ void cpasync16(uint32_t dst, const void* src) {
    asm volatile("cp.async.cg.shared.global [%0], [%1], 16;" :: "r"(dst), "l"(src));
}
#define CP_COMMIT() asm volatile("cp.async.commit_group;" ::: "memory")
#define CP_WAIT0()  asm volatile("cp.async.wait_group 0;" ::: "memory")

// =====================================================================
// 1) Encoder grouped conv -> A-format (bf16 hi/lo, SW128-swizzled) in g_hA
//    Tile: 32 groups x 32 batches. All threads parallel, coalesced x rows.
// =====================================================================
#define EGB 32
// smem floats: w[1920], bias[96], x[32*656]
#define ENC_W_OFF 0
#define ENC_B_OFF 1920
#define ENC_X_OFF 2016
#define ENC_XSTR  656
#define ENC_SMEM  ((ENC_X_OFF + 32 * ENC_XSTR) * 4)

__global__ void __launch_bounds__(256)
enc_conv(const float* __restrict__ x,
         const float* __restrict__ ew,
         const float* __restrict__ eb) {
    extern __shared__ __align__(16) float sf[];
    float* w_sm = sf + ENC_W_OFF;
    float* b_sm = sf + ENC_B_OFF;
    float* x_sm = sf + ENC_X_OFF;

    int g0 = blockIdx.x * EGB;
    int ng = G_TOT - g0; if (ng > EGB) ng = EGB;
    int nk = ng * 3;
    int kbase = g0 * 3;
    int t = threadIdx.x;

    for (int i = t; i < ng * 60; i += 256) w_sm[i] = ew[(size_t)g0 * 60 + i];
    for (int i = t; i < nk;      i += 256) b_sm[i] = eb[(size_t)g0 * 3 + i];
    __syncthreads();

    int nf4 = ng * 5;                   // float4 per x row
    int ntask = 32 * (nk >> 3);         // (b, k-octet) tasks

    for (int bc = 0; bc < BATCH; bc += 32) {
        // load x tile [32 b][ng*20] coalesced
        for (int idx = t; idx < 32 * 160; idx += 256) {
            int r = idx / 160, c = idx % 160;
            if (c < nf4) {
                float4 v = *(const float4*)(x + (size_t)(bc + r) * INLEN + (size_t)g0 * 20 + c * 4);
                *(float4*)(x_sm + r * ENC_XSTR + c * 4) = v;
            }
        }
        __syncthreads();

        for (int tau = t; tau < ntask; tau += 256) {
            int b   = tau / (nk >> 3);
            int oct = tau - b * (nk >> 3);
            int kl0 = oct * 8;
            float v[8];
            #pragma unroll
            for (int e = 0; e < 8; e++) {
                int kl = kl0 + e;
                int gl = kl / 3;
                int c  = kl - gl * 3;
                const float* xp = x_sm + b * ENC_XSTR + gl * 20;
                const float* wp = w_sm + gl * 60 + c * 20;
                float a = b_sm[kl];
                #pragma unroll
                for (int kk = 0; kk < KW; kk++) a = fmaf(xp[kk], wp[kk], a);
                v[e] = leaky(a);
            }
            uint32_t hi[4], lo[4];
            #pragma unroll
            for (int p = 0; p < 4; p++) {
                hi[p] = bf2pack(v[2 * p], v[2 * p + 1]);
                float h0 = __uint_as_float(hi[p] << 16);
                float h1 = __uint_as_float(hi[p] & 0xffff0000u);
                lo[p] = bf2pack(v[2 * p] - h0, v[2 * p + 1] - h1);
            }
            int m  = bc + b;
            int kg = kbase + kl0;
            int blk = kg >> 6, kin = kg & 63;
            uint32_t off = swz128((uint32_t)m * 128 + (uint32_t)(kin << 1));
            unsigned char* base = g_hA + (size_t)blk * ABLK_BYTES;
            *(uint4*)(base + off)         = make_uint4(hi[0], hi[1], hi[2], hi[3]);
            *(uint4*)(base + 16384 + off) = make_uint4(lo[0], lo[1], lo[2], lo[3]);
        }
        __syncthreads();
    }
}

// =====================================================================
// 2) Tensor-core GEMM via mma.sync (bf16 hi/lo, 3-pass, fp32 accum)
//    128x128 CTA tile, 16 warps (512 thr), warp tile 32x32, 2-stage pipe.
//    MODE 1: fp32 partials -> g_zpart[by][n][m]   (FC1 split-K)
//    MODE 2: fused bias + leaky -> out[n*128+m]   (FC2)
// =====================================================================
#define SMEM_GEMM (2 * 65536)

template <int MODE>
__global__ void __launch_bounds__(512, 1)
gemm_mma(const unsigned char* __restrict__ Aglob,
         const float* __restrict__ W,
         const float* __restrict__ bias,
         float* __restrict__ out,
         int N, int Kstride, int totalK, int splitLen) {
    extern __shared__ __align__(1024) unsigned char sm[];
    uint32_t smb = smem_u32(sm);
    int t = threadIdx.x, wid = t >> 5, L = t & 31;

    int n0   = blockIdx.x * 128;
    int kbeg = blockIdx.y * splitLen;
    int klen = min(splitLen, totalK - kbeg);
    int S    = (klen + 63) >> 6;
    int blk0 = kbeg >> 6;

    // W load assignment: 4 threads per n-row, each covers 16 k (4 float4)
    int wn = t >> 2;
    int wq = t & 3;
    const float* wrow = W + (size_t)(n0 + wn) * Kstride + kbeg;
    bool rvalid = (n0 + wn) < N;
    uint32_t wsoff[4];
    #pragma unroll
    for (int f = 0; f < 4; f++)
        wsoff[f] = swz128((uint32_t)wn * 128 + (uint32_t)((wq * 16 + f * 4) << 1));

    // ldmatrix per-lane addressing: addr = row*128 + (kbyte ^ ((row&7)<<4))
    int m0w = (wid >> 2) * 32;
    int nw0 = (wid & 3) * 32;
    uint32_t aRowOff = (uint32_t)(m0w + (L & 15)) * 128;
    uint32_t bRowOff = (uint32_t)(nw0 + (L & 15)) * 128;
    uint32_t pat     = (uint32_t)(L & 7) << 4;
    uint32_t kb0     = (uint32_t)(L >> 4) << 4;

    float acc[2][4][4];
    #pragma unroll
    for (int i = 0; i < 2; i++)
        #pragma unroll
        for (int j = 0; j < 4; j++)
            #pragma unroll
            for (int q = 0; q < 4; q++) acc[i][j][q] = 0.0f;

    // ---- prolog: stage 0 A via cp.async (32KB), W0 into regs ----
    float4 aW[4];
    {
        const char* src = (const char*)(Aglob + (size_t)blk0 * ABLK_BYTES) + t * 16;
        uint32_t dst = smb + t * 16;
        #pragma unroll
        for (int i = 0; i < 4; i++) cpasync16(dst + i * 8192, src + i * 8192);
        CP_COMMIT();
        #pragma unroll
        for (int f = 0; f < 4; f++) {
            int kk = wq * 16 + f * 4;
            aW[f] = (rvalid && kk < klen) ? *(const float4*)(wrow + kk)
                                          : make_float4(0.f, 0.f, 0.f, 0.f);
        }
    }

    for (int s = 0; s < S; s++) {
        uint32_t bufo = (uint32_t)(s & 1) * 65536;
        int lenS = min(64, klen - (s << 6));

        CP_WAIT0();   // stage-s A tile arrived

        // store W_s (convert fp32 -> bf16 hi/lo, swizzled)
        #pragma unroll
        for (int f = 0; f < 4; f++) {
            float x0 = aW[f].x, x1 = aW[f].y, x2 = aW[f].z, x3 = aW[f].w;
            uint32_t h01 = bf2pack(x0, x1);
            uint32_t h23 = bf2pack(x2, x3);
            float f0 = __uint_as_float(h01 << 16);
            float f1 = __uint_as_float(h01 & 0xffff0000u);
            float f2 = __uint_as_float(h23 << 16);
            float f3 = __uint_as_float(h23 & 0xffff0000u);
            uint32_t l01 = bf2pack(x0 - f0, x1 - f1);
            uint32_t l23 = bf2pack(x2 - f2, x3 - f3);
            *(uint2*)(sm + bufo + 32768 + wsoff[f]) = make_uint2(h01, h23);
            *(uint2*)(sm + bufo + 49152 + wsoff[f]) = make_uint2(l01, l23);
        }
        __syncthreads();

        // prefetch stage s+1
        if (s + 1 < S) {
            uint32_t nbufo = (uint32_t)((s + 1) & 1) * 65536;
            const char* src = (const char*)(Aglob + (size_t)(blk0 + s + 1) * ABLK_BYTES) + t * 16;
            uint32_t dst = smb + nbufo + t * 16;
            #pragma unroll
            for (int i = 0; i < 4; i++) cpasync16(dst + i * 8192, src + i * 8192);
            CP_COMMIT();
            int koff = (s + 1) << 6;
            #pragma unroll
            for (int f = 0; f < 4; f++) {
                int kk = koff + wq * 16 + f * 4;
                aW[f] = (rvalid && kk < klen) ? *(const float4*)(wrow + kk)
                                              : make_float4(0.f, 0.f, 0.f, 0.f);
            }
        }

        // ---- compute stage s ----
        uint32_t aBase = smb + bufo + aRowOff;            // A hi tile
        uint32_t bBase = smb + bufo + 32768 + bRowOff;    // W hi tile
        int nk16 = lenS >> 4;
        for (int ks = 0; ks < nk16; ks++) {
            uint32_t kx = (kb0 + (uint32_t)ks * 32) ^ pat;
            uint32_t Ah[2][4], Al[2][4], Bh[2][4], Bl[2][4];
            #pragma unroll
            for (int i = 0; i < 2; i++) {
                ldsm4(Ah[i], aBase + i * 2048 + kx);
                ldsm4(Al[i], aBase + 16384 + i * 2048 + kx);
            }
            #pragma unroll
            for (int p = 0; p < 2; p++) {
                ldsm4(Bh[p], bBase + p * 2048 + kx);
                ldsm4(Bl[p], bBase + 16384 + p * 2048 + kx);
            }
            #pragma unroll
            for (int i = 0; i < 2; i++)
                #pragma unroll
                for (int j = 0; j < 4; j++) {
                    int p = j >> 1, q = j & 1;
                    mma16816(acc[i][j], Ah[i], Bh[p][q], Bh[p][q + 2]);
                    mma16816(acc[i][j], Ah[i], Bl[p][q], Bl[p][q + 2]);
                    mma16816(acc[i][j], Al[i], Bh[p][q], Bh[p][q + 2]);
                }
        }
        __syncthreads();
    }

    // ---- epilogue ----
    int row0 = m0w + (L >> 2);
    int col0 = nw0 + (L & 3) * 2;
    #pragma unroll
    for (int i = 0; i < 2; i++)
        #pragma unroll
        for (int j = 0; j < 4; j++) {
            int row = row0 + i * 16;
            int col = col0 + j * 8;
            if (MODE == 1) {
                float* base = out + ((size_t)blockIdx.y * NPAD + (n0 + col)) * 128 + row;
                base[0]   = acc[i][j][0];
                base[128] = acc[i][j][1];
                base[8]   = acc[i][j][2];
                base[136] = acc[i][j][3];
            } else {
                int n = n0 + col;
                if (n < N) {
                    float b0 = bias[n];
                    out[(size_t)n * 128 + row]     = leaky(acc[i][j][0] + b0);
                    out[(size_t)n * 128 + row + 8] = leaky(acc[i][j][2] + b0);
                }
                if (n + 1 < N) {
                    float b1 = bias[n + 1];
                    out[(size_t)(n + 1) * 128 + row]     = leaky(acc[i][j][1] + b1);
                    out[(size_t)(n + 1) * 128 + row + 8] = leaky(acc[i][j][3] + b1);
                }
            }
        }
}

// =====================================================================
// 3) FC1 reduction + bias + leaky -> z in A-format (bf16 hi/lo) g_zA
// =====================================================================
__global__ void reduce_z(const float* __restrict__ b1) {
    int n = blockIdx.x;
    int m = threadIdx.x;
    float s = b1[n];
    #pragma unroll
    for (int ks = 0; ks < KSPLIT; ks++)
        s += g_zpart[((size_t)ks * NPAD + n) * 128 + m];
    float val = leaky(s);
    __nv_bfloat16 hi = __float2bfloat16(val);
    __nv_bfloat16 lo = __float2bfloat16(val - __bfloat162float(hi));
    int blk = n >> 6;
    int kin = n & 63;
    uint32_t off = swz128((uint32_t)m * 128 + (uint32_t)(kin << 1));
    unsigned char* base = g_zA + (size_t)blk * ABLK_BYTES;
    *(__nv_bfloat16*)(base + off)         = hi;
    *(__nv_bfloat16*)(base + 16384 + off) = lo;
}

// =====================================================================
// 4) Decoder grouped deconv + sigmoid
//    Tile: 32 groups x 32 batches, staged output rows, coalesced writes.
// =====================================================================
// smem floats: w[1920], db[32], dt[96*36], out[32*656]
#define DEC_W_OFF  0
#define DEC_B_OFF  1920
#define DEC_DT_OFF 1952
#define DEC_DTSTR  36
#define DEC_O_OFF  (DEC_DT_OFF + 96 * DEC_DTSTR)
#define DEC_OSTR   656
#define DEC_SMEM   ((DEC_O_OFF + 32 * DEC_OSTR) * 4)

__global__ void __launch_bounds__(256)
dec_conv(const float* __restrict__ dw,
         const float* __restrict__ db,
         float* __restrict__ out) {
    extern __shared__ __align__(16) float sf[];
    float* w_sm  = sf + DEC_W_OFF;
    float* db_sm = sf + DEC_B_OFF;
    float* dt_sm = sf + DEC_DT_OFF;
    float* o_sm  = sf + DEC_O_OFF;

    int g0 = blockIdx.x * EGB;
    int ng = G_TOT - g0; if (ng > EGB) ng = EGB;
    int nk = ng * 3;
    int t  = threadIdx.x;

    for (int i = t; i < ng * 60; i += 256) w_sm[i] = dw[(size_t)g0 * 60 + i];
    for (int i = t; i < ng;      i += 256) db_sm[i] = db[g0 + i];
    __syncthreads();

    for (int bc = 0; bc < BATCH; bc += 32) {
        // load dT tile [nk][32 b] (rows of g_dT are [n][128 b])
        for (int idx = t; idx < nk * 8; idx += 256) {
            int n = idx >> 3, q = idx & 7;
            float4 v = *(const float4*)(g_dT + (size_t)(g0 * 3 + n) * 128 + bc + q * 4);
            *(float4*)(dt_sm + n * DEC_DTSTR + q * 4) = v;
        }
        __syncthreads();

        // compute: one (g, b) pair per task -> 20 outputs into o_sm
        int ntask = ng * 32;
        for (int tau = t; tau < ntask; tau += 256) {
            int g = tau >> 5, b = tau & 31;
            float d0 = dt_sm[(3 * g + 0) * DEC_DTSTR + b];
            float d1 = dt_sm[(3 * g + 1) * DEC_DTSTR + b];
            float d2 = dt_sm[(3 * g + 2) * DEC_DTSTR + b];
            float bv = db_sm[g];
            const float* wp = w_sm + g * 60;
            float* op = o_sm + b * DEC_OSTR + g * 20;
            #pragma unroll
            for (int kk = 0; kk < KW; kk++) {
                float v = fmaf(d0, wp[kk], fmaf(d1, wp[20 + kk], fmaf(d2, wp[40 + kk], bv)));
                op[kk] = 1.0f / (1.0f + __expf(-v));
            }
        }
        __syncthreads();

        // write out tile [32 b][ng*20] coalesced
        int nf4 = ng * 5;
        for (int idx = t; idx < 32 * 160; idx += 256) {
            int r = idx / 160, c = idx % 160;
            if (c < nf4) {
                float4 v = *(const float4*)(o_sm + r * DEC_OSTR + c * 4);
                *(float4*)(out + (size_t)(bc + r) * INLEN + (size_t)g0 * 20 + c * 4) = v;
            }
        }
        __syncthreads();
    }
}

// =====================================================================
// launcher — graph-capturable, allocation-free
// =====================================================================
extern "C" void kernel_launch(void* const* d_in, const int* in_sizes, int n_in,
                              void* d_out, int out_size) {
    const float* x   = (const float*)d_in[0];
    const float* ew  = (const float*)d_in[1];
    const float* eb  = (const float*)d_in[2];
    const float* efw = (const float*)d_in[3];
    const float* efb = (const float*)d_in[4];
    const float* dfw = (const float*)d_in[5];
    const float* dfb = (const float*)d_in[6];
    const float* dw  = (const float*)d_in[7];
    const float* db  = (const float*)d_in[8];
    float* out = (float*)d_out;

    unsigned char *hA, *zA;
    float *zpart, *dT;
    cudaGetSymbolAddress((void**)&hA,    g_hA);
    cudaGetSymbolAddress((void**)&zA,    g_zA);
    cudaGetSymbolAddress((void**)&zpart, g_zpart);
    cudaGetSymbolAddress((void**)&dT,    g_dT);

    cudaFuncSetAttribute(gemm_mma<1>, cudaFuncAttributeMaxDynamicSharedMemorySize, SMEM_GEMM);
    cudaFuncSetAttribute(gemm_mma<2>, cudaFuncAttributeMaxDynamicSharedMemorySize, SMEM_GEMM);
    cudaFuncSetAttribute(enc_conv,    cudaFuncAttributeMaxDynamicSharedMemorySize, ENC_SMEM);
    cudaFuncSetAttribute(dec_conv,    cudaFuncAttributeMaxDynamicSharedMemorySize, DEC_SMEM);

    // 1) encoder grouped conv -> h (bf16 hi/lo, A-format)
    enc_conv<<<(G_TOT + EGB - 1) / EGB, 256, ENC_SMEM>>>(x, ew, eb);
    // 2) FC1 mma GEMM (split-K) -> fp32 partials
    gemm_mma<1><<<dim3(16, KSPLIT), 512, SMEM_GEMM>>>(hA, efw, nullptr, zpart,
                                                      LAT, KDIM, KDIM, SPLIT_LEN);
    // 3) reduce + bias + leaky -> z (bf16 hi/lo, A-format)
    reduce_z<<<LAT, 128>>>(efb);
    // 4) FC2 mma GEMM, fused bias+leaky -> d^T (fp32)
    gemm_mma<2><<<dim3((KDIM + 127) / 128, 1), 512, SMEM_GEMM>>>(zA, dfw, dfb, dT,
                                                                 KDIM, LAT, LAT, 2048);
    // 5) decoder deconv + sigmoid -> out
    dec_conv<<<(G_TOT + EGB - 1) / EGB, 256, DEC_SMEM>>>(dw, db, out);
}

// round 13
// speedup vs baseline: 1.5500x; 1.5500x over previous
#include <cuda_runtime.h>
#include <cuda_bf16.h>
#include <cstdint>

// ---------------- problem constants ----------------
#define BATCH   128
#define G_TOT   10000
#define KW      20
#define LAT     2000
#define KDIM    30000      // G*C
#define INLEN   200000
#define NPAD    2048
#define SPLIT_LEN 1216     // FC1 split-K length (19 blocks of 64)
#define KSPLIT  25         // last split = 816
#define NBLK_H  469        // ceil(30000/64)
#define NBLK_Z  32         // ceil(2000/64)

// Per 64-k block: [128 m][64 k] bf16, SW128 swizzled rows; hi 16KB then lo 16KB.
#define ABLK_BYTES 32768

// ---------------- device scratch (static, no allocation) ----------------
__device__ __align__(16) unsigned char g_hA[(size_t)NBLK_H * ABLK_BYTES];
__device__ __align__(16) unsigned char g_zA[(size_t)NBLK_Z * ABLK_BYTES];
__device__ float g_zpart[(size_t)KSPLIT * NPAD * 128];
__device__ float g_dT[(size_t)KDIM * 128];

// ---------------- helpers ----------------
__device__ __forceinline__ uint32_t smem_u32(const void* p) {
    uint32_t a;
    asm("{ .reg .u64 t; cvta.to.shared.u64 t, %1; cvt.u32.u64 %0, t; }" : "=r"(a) : "l"(p));
    return a;
}
__device__ __forceinline__ uint32_t swz128(uint32_t off) { return off ^ ((off >> 3) & 0x70); }
__device__ __forceinline__ float leaky(float v) { return v >= 0.0f ? v : 0.1f * v; }

// pack two fp32 -> bf16x2 (lo half = a, hi half = b)
__device__ __forceinline__ uint32_t bf2pack(float a, float b) {
    uint32_t r;
    asm("cvt.rn.bf16x2.f32 %0, %1, %2;" : "=r"(r) : "f"(b), "f"(a));
    return r;
}

__device__ __forceinline__ void ldsm4(uint32_t* r, uint32_t addr) {
    asm volatile("ldmatrix.sync.aligned.m8n8.x4.shared.b16 {%0,%1,%2,%3}, [%4];"
        : "=r"(r[0]), "=r"(r[1]), "=r"(r[2]), "=r"(r[3]) : "r"(addr));
}

__device__ __forceinline__ void mma16816(float* c, const uint32_t* a, uint32_t b0, uint32_t b1) {
    asm volatile("mma.sync.aligned.m16n8k16.row.col.f32.bf16.bf16.f32 "
        "{%0,%1,%2,%3}, {%4,%5,%6,%7}, {%8,%9}, {%0,%1,%2,%3};"
        : "+f"(c[0]), "+f"(c[1]), "+f"(c[2]), "+f"(c[3])
        : "r"(a[0]), "r"(a[1]), "r"(a[2]), "r"(a[3]), "r"(b0), "r"(b1));
}

__device__ __forceinline__ void cpasync16(uint32_t dst, const void* src) {
    asm volatile("cp.async.cg.shared.global [%0], [%1], 16;" :: "r"(dst), "l"(src));
}
#define CP_COMMIT() asm volatile("cp.async.commit_group;" ::: "memory")
#define CP_WAIT0()  asm volatile("cp.async.wait_group 0;" ::: "memory")

// =====================================================================
// 1) Encoder grouped conv -> A-format (bf16 hi/lo, SW128-swizzled) in g_hA
// =====================================================================
#define GB 64
__global__ void enc_conv(const float* __restrict__ x,
                         const float* __restrict__ ew,
                         const float* __restrict__ eb) {
    __shared__ float w_s[GB * 60];
    __shared__ float b_s[GB * 3];
    __shared__ float x_s[GB * 20];
    __shared__ float ht_s[GB * 3 * 33];

    int g0 = blockIdx.x * GB;
    int ng = G_TOT - g0; if (ng > GB) ng = GB;
    int nk = ng * 3;
    int k0 = g0 * 3;                 // multiple of 192
    int t  = threadIdx.x;

    for (int i = t; i < ng * 60; i += 256) w_s[i] = ew[(size_t)g0 * 60 + i];
    for (int i = t; i < nk;      i += 256) b_s[i] = eb[(size_t)g0 * 3 + i];
    __syncthreads();

    for (int bc = 0; bc < BATCH; bc += 32) {
        for (int bb = 0; bb < 32; bb++) {
            int b = bc + bb;
            for (int i = t; i < ng * 20; i += 256)
                x_s[i] = x[(size_t)b * INLEN + (size_t)g0 * 20 + i];
            __syncthreads();
            if (t < nk) {
                const float* wp = &w_s[t * 20];
                const float* xp = &x_s[(t / 3) * 20];
                float acc = b_s[t];
                #pragma unroll
                for (int k = 0; k < KW; k++) acc = fmaf(xp[k], wp[k], acc);
                ht_s[t * 33 + bb] = leaky(acc);
            }
            __syncthreads();
        }
        int npair = nk >> 1;
        for (int idx = t; idx < npair * 32; idx += 256) {
            int kp = idx % npair;
            int bb = idx / npair;
            int m  = bc + bb;
            float v0 = ht_s[(2 * kp)     * 33 + bb];
            float v1 = ht_s[(2 * kp + 1) * 33 + bb];
            uint32_t hi = bf2pack(v0, v1);
            float h0 = __uint_as_float(hi << 16);
            float h1 = __uint_as_float(hi & 0xffff0000u);
            uint32_t lo = bf2pack(v0 - h0, v1 - h1);
            int k   = 2 * kp;
            int blk = (k0 + k) >> 6;
            int kin = k & 63;
            uint32_t off = swz128((uint32_t)m * 128 + (uint32_t)(kin << 1));
            unsigned char* base = g_hA + (size_t)blk * ABLK_BYTES;
            *(uint32_t*)(base + off)         = hi;
            *(uint32_t*)(base + 16384 + off) = lo;
        }
        __syncthreads();
    }
}

// =====================================================================
// 2) Tensor-core GEMM via mma.sync (bf16 hi/lo, 3-pass, fp32 accum)
//    128x128 CTA tile, 8 warps, warp tile 64x32, 2-stage cp.async pipe.
//    MMA issue is PASS-MAJOR: all 16 AhBh, then 16 AhBl, then 16 AlBh —
//    16-accumulator reuse distance kills the RAW latency chain that held
//    the R8 version at 37% tensor util.
//    MODE 1: fp32 partials -> g_zpart[by][n][m]   (FC1 split-K)
//    MODE 2: fused bias + leaky -> out[n*128+m]   (FC2)
// =====================================================================
#define SMEM_GEMM (2 * 65536)

template <int MODE>
__global__ void __launch_bounds__(256, 1)
gemm_mma(const unsigned char* __restrict__ Aglob,
         const float* __restrict__ W,
         const float* __restrict__ bias,
         float* __restrict__ out,
         int N, int Kstride, int totalK, int splitLen) {
    extern __shared__ __align__(1024) unsigned char sm[];
    uint32_t smb = smem_u32(sm);
    int t = threadIdx.x, wid = t >> 5, L = t & 31;

    int n0   = blockIdx.x * 128;
    int kbeg = blockIdx.y * splitLen;
    int klen = min(splitLen, totalK - kbeg);
    int S    = (klen + 63) >> 6;
    int blk0 = kbeg >> 6;

    // W load assignment: 2 threads per n-row, each covers 32 k as 8 float4
    int wn = t >> 1;
    int wh = t & 1;
    const float* wrow = W + (size_t)(n0 + wn) * Kstride + kbeg;
    bool rvalid = (n0 + wn) < N;
    uint32_t wsoff[8];
    #pragma unroll
    for (int f = 0; f < 8; f++)
        wsoff[f] = swz128((uint32_t)wn * 128 + (uint32_t)((wh * 32 + f * 4) << 1));

    // ldmatrix per-lane addressing: addr = row*128 + (kbyte ^ ((row&7)<<4))
    int m0w = (wid >> 2) * 64;
    int nw0 = (wid & 3) * 32;
    uint32_t aRowOff = (uint32_t)(m0w + (L & 15)) * 128;
    uint32_t bRowOff = (uint32_t)(nw0 + (L & 15)) * 128;
    uint32_t pat     = (uint32_t)(L & 7) << 4;
    uint32_t kb0     = (uint32_t)(L >> 4) << 4;

    float acc[4][4][4];
    #pragma unroll
    for (int i = 0; i < 4; i++)
        #pragma unroll
        for (int j = 0; j < 4; j++)
            #pragma unroll
            for (int q = 0; q < 4; q++) acc[i][j][q] = 0.0f;

    // ---- prolog: stage 0 A via cp.async, W0 into regs ----
    float4 aW[8];
    {
        const char* src = (const char*)(Aglob + (size_t)blk0 * ABLK_BYTES) + t * 16;
        uint32_t dst = smb + t * 16;
        #pragma unroll
        for (int i = 0; i < 8; i++) cpasync16(dst + i * 4096, src + i * 4096);
        CP_COMMIT();
        #pragma unroll
        for (int f = 0; f < 8; f++) {
            int kk = wh * 32 + f * 4;
            aW[f] = (rvalid && kk < klen) ? *(const float4*)(wrow + kk)
                                          : make_float4(0.f, 0.f, 0.f, 0.f);
        }
    }

    for (int s = 0; s < S; s++) {
        uint32_t bufo = (uint32_t)(s & 1) * 65536;
        int lenS = min(64, klen - (s << 6));

        CP_WAIT0();   // stage-s A tile arrived

        // store W_s (convert fp32 -> bf16 hi/lo, swizzled)
        #pragma unroll
        for (int f = 0; f < 8; f++) {
            float x0 = aW[f].x, x1 = aW[f].y, x2 = aW[f].z, x3 = aW[f].w;
            uint32_t h01 = bf2pack(x0, x1);
            uint32_t h23 = bf2pack(x2, x3);
            float f0 = __uint_as_float(h01 << 16);
            float f1 = __uint_as_float(h01 & 0xffff0000u);
            float f2 = __uint_as_float(h23 << 16);
            float f3 = __uint_as_float(h23 & 0xffff0000u);
            uint32_t l01 = bf2pack(x0 - f0, x1 - f1);
            uint32_t l23 = bf2pack(x2 - f2, x3 - f3);
            *(uint2*)(sm + bufo + 32768 + wsoff[f]) = make_uint2(h01, h23);
            *(uint2*)(sm + bufo + 49152 + wsoff[f]) = make_uint2(l01, l23);
        }
        __syncthreads();

        // prefetch stage s+1
        if (s + 1 < S) {
            uint32_t nbufo = (uint32_t)((s + 1) & 1) * 65536;
            const char* src = (const char*)(Aglob + (size_t)(blk0 + s + 1) * ABLK_BYTES) + t * 16;
            uint32_t dst = smb + nbufo + t * 16;
            #pragma unroll
            for (int i = 0; i < 8; i++) cpasync16(dst + i * 4096, src + i * 4096);
            CP_COMMIT();
            int koff = (s + 1) << 6;
            #pragma unroll
            for (int f = 0; f < 8; f++) {
                int kk = koff + wh * 32 + f * 4;
                aW[f] = (rvalid && kk < klen) ? *(const float4*)(wrow + kk)
                                              : make_float4(0.f, 0.f, 0.f, 0.f);
            }
        }

        // ---- compute stage s ----
        uint32_t aBase = smb + bufo + aRowOff;            // A hi tile
        uint32_t bBase = smb + bufo + 32768 + bRowOff;    // W hi tile
        int nk16 = lenS >> 4;
        for (int ks = 0; ks < nk16; ks++) {
            uint32_t kx = (kb0 + (uint32_t)ks * 32) ^ pat;
            uint32_t Ah[4][4], Al[4][4], Bh[2][4], Bl[2][4];
            #pragma unroll
            for (int i = 0; i < 4; i++) {
                ldsm4(Ah[i], aBase + i * 2048 + kx);
                ldsm4(Al[i], aBase + 16384 + i * 2048 + kx);
            }
            #pragma unroll
            for (int p = 0; p < 2; p++) {
                ldsm4(Bh[p], bBase + p * 2048 + kx);
                ldsm4(Bl[p], bBase + 16384 + p * 2048 + kx);
            }
            // pass-major issue: 16 independent accumulators between reuses
            #pragma unroll
            for (int i = 0; i < 4; i++)
                #pragma unroll
                for (int j = 0; j < 4; j++)
                    mma16816(acc[i][j], Ah[i], Bh[j >> 1][j & 1], Bh[j >> 1][(j & 1) + 2]);
            #pragma unroll
            for (int i = 0; i < 4; i++)
                #pragma unroll
                for (int j = 0; j < 4; j++)
                    mma16816(acc[i][j], Ah[i], Bl[j >> 1][j & 1], Bl[j >> 1][(j & 1) + 2]);
            #pragma unroll
            for (int i = 0; i < 4; i++)
                #pragma unroll
                for (int j = 0; j < 4; j++)
                    mma16816(acc[i][j], Al[i], Bh[j >> 1][j & 1], Bh[j >> 1][(j & 1) + 2]);
        }
        __syncthreads();
    }

    // ---- epilogue: write accumulators ----
    int row0 = m0w + (L >> 2);
    int col0 = nw0 + (L & 3) * 2;
    #pragma unroll
    for (int i = 0; i < 4; i++)
        #pragma unroll
        for (int j = 0; j < 4; j++) {
            int row = row0 + i * 16;
            int col = col0 + j * 8;
            if (MODE == 1) {
                float* base = out + ((size_t)blockIdx.y * NPAD + (n0 + col)) * 128 + row;
                base[0]   = acc[i][j][0];
                base[128] = acc[i][j][1];
                base[8]   = acc[i][j][2];
                base[136] = acc[i][j][3];
            } else {
                int n = n0 + col;
                if (n < N) {
                    float b0 = bias[n];
                    out[(size_t)n * 128 + row]     = leaky(acc[i][j][0] + b0);
                    out[(size_t)n * 128 + row + 8] = leaky(acc[i][j][2] + b0);
                }
                if (n + 1 < N) {
                    float b1 = bias[n + 1];
                    out[(size_t)(n + 1) * 128 + row]     = leaky(acc[i][j][1] + b1);
                    out[(size_t)(n + 1) * 128 + row + 8] = leaky(acc[i][j][3] + b1);
                }
            }
        }
}

// =====================================================================
// 3) FC1 reduction + bias + leaky -> z in A-format (bf16 hi/lo) g_zA
// =====================================================================
__global__ void reduce_z(const float* __restrict__ b1) {
    int n = blockIdx.x;
    int m = threadIdx.x;
    float s = b1[n];
    #pragma unroll
    for (int ks = 0; ks < KSPLIT; ks++)
        s += g_zpart[((size_t)ks * NPAD + n) * 128 + m];
    float val = leaky(s);
    __nv_bfloat16 hi = __float2bfloat16(val);
    __nv_bfloat16 lo = __float2bfloat16(val - __bfloat162float(hi));
    int blk = n >> 6;
    int kin = n & 63;
    uint32_t off = swz128((uint32_t)m * 128 + (uint32_t)(kin << 1));
    unsigned char* base = g_zA + (size_t)blk * ABLK_BYTES;
    *(__nv_bfloat16*)(base + off)         = hi;
    *(__nv_bfloat16*)(base + 16384 + off) = lo;
}

// =====================================================================
// 4) Decoder grouped deconv + sigmoid
// =====================================================================
__global__ void dec_conv(const float* __restrict__ dw,
                         const float* __restrict__ db,
                         float* __restrict__ out) {
    __shared__ float w_s[GB * 60];
    __shared__ float b_s[GB];
    __shared__ float dt_s[GB * 3 * 33];

    int g0 = blockIdx.x * GB;
    int ng = G_TOT - g0; if (ng > GB) ng = GB;
    int nk = ng * 3;
    int t  = threadIdx.x;

    for (int i = t; i < ng * 60; i += 256) w_s[i] = dw[(size_t)g0 * 60 + i];
    for (int i = t; i < ng;      i += 256) b_s[i] = db[g0 + i];
    __syncthreads();

    for (int bc = 0; bc < BATCH; bc += 32) {
        for (int e = t; e < nk * 32; e += 256) {
            int k = e >> 5, bb = e & 31;
            dt_s[k * 33 + bb] = g_dT[(size_t)(g0 * 3 + k) * 128 + bc + bb];
        }
        __syncthreads();
        for (int bb = 0; bb < 32; bb++) {
            int b = bc + bb;
            for (int idx = t; idx < ng * 20; idx += 256) {
                int g  = idx / 20;
                int kk = idx - g * 20;
                float v = fmaf(dt_s[(g * 3 + 0) * 33 + bb], w_s[g * 60 +      kk],
                          fmaf(dt_s[(g * 3 + 1) * 33 + bb], w_s[g * 60 + 20 + kk],
                          fmaf(dt_s[(g * 3 + 2) * 33 + bb], w_s[g * 60 + 40 + kk],
                               b_s[g])));
                out[(size_t)b * INLEN + (size_t)g0 * 20 + idx] =
                    1.0f / (1.0f + __expf(-v));
            }
        }
        __syncthreads();
    }
}

// =====================================================================
// launcher — graph-capturable, allocation-free
// =====================================================================
extern "C" void kernel_launch(void* const* d_in, const int* in_sizes, int n_in,
                              void* d_out, int out_size) {
    const float* x   = (const float*)d_in[0];
    const float* ew  = (const float*)d_in[1];
    const float* eb  = (const float*)d_in[2];
    const float* efw = (const float*)d_in[3];
    const float* efb = (const float*)d_in[4];
    const float* dfw = (const float*)d_in[5];
    const float* dfb = (const float*)d_in[6];
    const float* dw  = (const float*)d_in[7];
    const float* db  = (const float*)d_in[8];
    float* out = (float*)d_out;

    unsigned char *hA, *zA;
    float *zpart, *dT;
    cudaGetSymbolAddress((void**)&hA,    g_hA);
    cudaGetSymbolAddress((void**)&zA,    g_zA);
    cudaGetSymbolAddress((void**)&zpart, g_zpart);
    cudaGetSymbolAddress((void**)&dT,    g_dT);

    cudaFuncSetAttribute(gemm_mma<1>, cudaFuncAttributeMaxDynamicSharedMemorySize, SMEM_GEMM);
    cudaFuncSetAttribute(gemm_mma<2>, cudaFuncAttributeMaxDynamicSharedMemorySize, SMEM_GEMM);

    // 1) encoder grouped conv -> h (bf16 hi/lo, A-format)
    enc_conv<<<(G_TOT + GB - 1) / GB, 256>>>(x, ew, eb);
    // 2) FC1 mma GEMM (split-K) -> fp32 partials
    gemm_mma<1><<<dim3(16, KSPLIT), 256, SMEM_GEMM>>>(hA, efw, nullptr, zpart,
                                                      LAT, KDIM, KDIM, SPLIT_LEN);
    // 3) reduce + bias + leaky -> z (bf16 hi/lo, A-format)
    reduce_z<<<LAT, 128>>>(efb);
    // 4) FC2 mma GEMM, fused bias+leaky -> d^T (fp32)
    gemm_mma<2><<<dim3((KDIM + 127) / 128, 1), 256, SMEM_GEMM>>>(zA, dfw, dfb, dT,
                                                                 KDIM, LAT, LAT, 2048);
    // 5) decoder deconv + sigmoid -> out
    dec_conv<<<(G_TOT + GB - 1) / GB, 256>>>(dw, db, out);
}

// round 15
// speedup vs baseline: 1.5621x; 1.0078x over previous
#include <cuda_runtime.h>
#include <cuda_bf16.h>
#include <cstdint>

// ---------------- problem constants ----------------
#define BATCH   128
#define G_TOT   10000
#define KW      20
#define LAT     2000
#define KDIM    30000      // G*C
#define INLEN   200000
#define NPAD    2048
#define SPLIT_LEN 1216     // FC1 split-K length (19 blocks of 64)
#define KSPLIT  25         // last split = 816
#define NBLK_H  469        // ceil(30000/64)
#define NBLK_Z  32         // ceil(2000/64)

// Per 64-k block: [128 m][64 k] bf16, SW128 swizzled rows; hi 16KB then lo 16KB.
#define ABLK_BYTES 32768

// ---------------- device scratch (static, no allocation) ----------------
__device__ __align__(16) unsigned char g_hA[(size_t)NBLK_H * ABLK_BYTES];
__device__ __align__(16) unsigned char g_zA[(size_t)NBLK_Z * ABLK_BYTES];
__device__ float g_zpart[(size_t)KSPLIT * NPAD * 128];
__device__ float g_dT[(size_t)KDIM * 128];

// ---------------- helpers ----------------
__device__ __forceinline__ uint32_t smem_u32(const void* p) {
    uint32_t a;
    asm("{ .reg .u64 t; cvta.to.shared.u64 t, %1; cvt.u32.u64 %0, t; }" : "=r"(a) : "l"(p));
    return a;
}
__device__ __forceinline__ uint32_t swz128(uint32_t off) { return off ^ ((off >> 3) & 0x70); }
__device__ __forceinline__ float leaky(float v) { return v >= 0.0f ? v : 0.1f * v; }

// pack two fp32 -> bf16x2 (lo half = a, hi half = b)
__device__ __forceinline__ uint32_t bf2pack(float a, float b) {
    uint32_t r;
    asm("cvt.rn.bf16x2.f32 %0, %1, %2;" : "=r"(r) : "f"(b), "f"(a));
    return r;
}

__device__ __forceinline__ void ldsm4(uint32_t* r, uint32_t addr) {
    asm volatile("ldmatrix.sync.aligned.m8n8.x4.shared.b16 {%0,%1,%2,%3}, [%4];"
        : "=r"(r[0]), "=r"(r[1]), "=r"(r[2]), "=r"(r[3]) : "r"(addr));
}

__device__ __forceinline__ void mma16816(float* c, const uint32_t* a, uint32_t b0, uint32_t b1) {
    asm volatile("mma.sync.aligned.m16n8k16.row.col.f32.bf16.bf16.f32 "
        "{%0,%1,%2,%3}, {%4,%5,%6,%7}, {%8,%9}, {%0,%1,%2,%3};"
        : "+f"(c[0]), "+f"(c[1]), "+f"(c[2]), "+f"(c[3])
        : "r"(a[0]), "r"(a[1]), "r"(a[2]), "r"(a[3]), "r"(b0), "r"(b1));
}

__device__ __forceinline__ void cpasync16(uint32_t dst, const void* src) {
    asm volatile("cp.async.cg.shared.global [%0], [%1], 16;" :: "r"(dst), "l"(src));
}
#define CP_COMMIT() asm volatile("cp.async.commit_group;" ::: "memory")
#define CP_WAIT1()  asm volatile("cp.async.wait_group 1;" ::: "memory")

// =====================================================================
// 1) Encoder grouped conv -> A-format (bf16 hi/lo, SW128-swizzled) in g_hA
// =====================================================================
#define GB 64
__global__ void enc_conv(const float* __restrict__ x,
                         const float* __restrict__ ew,
                         const float* __restrict__ eb) {
    __shared__ float w_s[GB * 60];
    __shared__ float b_s[GB * 3];
    __shared__ float x_s[GB * 20];
    __shared__ float ht_s[GB * 3 * 33];

    int g0 = blockIdx.x * GB;
    int ng = G_TOT - g0; if (ng > GB) ng = GB;
    int nk = ng * 3;
    int k0 = g0 * 3;                 // multiple of 192
    int t  = threadIdx.x;

    for (int i = t; i < ng * 60; i += 256) w_s[i] = ew[(size_t)g0 * 60 + i];
    for (int i = t; i < nk;      i += 256) b_s[i] = eb[(size_t)g0 * 3 + i];
    __syncthreads();

    for (int bc = 0; bc < BATCH; bc += 32) {
        for (int bb = 0; bb < 32; bb++) {
            int b = bc + bb;
            for (int i = t; i < ng * 20; i += 256)
                x_s[i] = x[(size_t)b * INLEN + (size_t)g0 * 20 + i];
            __syncthreads();
            if (t < nk) {
                const float* wp = &w_s[t * 20];
                const float* xp = &x_s[(t / 3) * 20];
                float acc = b_s[t];
                #pragma unroll
                for (int k = 0; k < KW; k++) acc = fmaf(xp[k], wp[k], acc);
                ht_s[t * 33 + bb] = leaky(acc);
            }
            __syncthreads();
        }
        int npair = nk >> 1;
        for (int idx = t; idx < npair * 32; idx += 256) {
            int kp = idx % npair;
            int bb = idx / npair;
            int m  = bc + bb;
            float v0 = ht_s[(2 * kp)     * 33 + bb];
            float v1 = ht_s[(2 * kp + 1) * 33 + bb];
            uint32_t hi = bf2pack(v0, v1);
            float h0 = __uint_as_float(hi << 16);
            float h1 = __uint_as_float(hi & 0xffff0000u);
            uint32_t lo = bf2pack(v0 - h0, v1 - h1);
            int k   = 2 * kp;
            int blk = (k0 + k) >> 6;
            int kin = k & 63;
            uint32_t off = swz128((uint32_t)m * 128 + (uint32_t)(kin << 1));
            unsigned char* base = g_hA + (size_t)blk * ABLK_BYTES;
            *(uint32_t*)(base + off)         = hi;
            *(uint32_t*)(base + 16384 + off) = lo;
        }
        __syncthreads();
    }
}

// =====================================================================
// 2) Tensor-core GEMM via mma.sync (bf16 hi/lo, 3-pass, fp32 accum)
//    128x128 CTA tile, 8 warps, warp tile 64x32.
//    Single-barrier pipeline: A triple-buffered (cp.async), W double-
//    buffered; W convert/store for s+1 and A prefetch for s+2 sit in the
//    SAME block as stage-s MMAs so ptxas interleaves them into the MMA
//    shadow. Epilogues stage through smem for coalesced global writes.
//    MODE 1: fp32 partials -> g_zpart[by][n][m]   (FC1 split-K)
//    MODE 2: fused bias + leaky -> out[n*128+m]   (FC2)
// =====================================================================
#define ABUF(i) ((uint32_t)(i) * 32768u)        // 3 x 32KB : 0,32K,64K
#define WBUF(i) (98304u + (uint32_t)(i) * 32768u) // 2 x 32KB : 96K,128K
#define SMEM_GEMM (160 * 1024)
#define EPI_STRIDE 136                           // padded fp32 row (conflict-free)

template <int MODE>
__global__ void __launch_bounds__(256, 1)
gemm_mma(const unsigned char* __restrict__ Aglob,
         const float* __restrict__ W,
         const float* __restrict__ bias,
         float* __restrict__ out,
         int N, int Kstride, int totalK, int splitLen) {
    extern __shared__ __align__(1024) unsigned char sm[];
    uint32_t smb = smem_u32(sm);
    int t = threadIdx.x, wid = t >> 5, L = t & 31;

    int n0   = blockIdx.x * 128;
    int kbeg = blockIdx.y * splitLen;
    int klen = min(splitLen, totalK - kbeg);
    int S    = (klen + 63) >> 6;
    int blk0 = kbeg >> 6;

    // W load assignment: 2 threads per n-row, each covers 32 k as 8 float4
    int wn = t >> 1;
    int wh = t & 1;
    const float* wrow = W + (size_t)(n0 + wn) * Kstride + kbeg;
    bool rvalid = (n0 + wn) < N;
    // paired (16B) store offsets: f2 covers k-octet wh*32 + f2*8
    uint32_t wsoff4[4];
    #pragma unroll
    for (int f2 = 0; f2 < 4; f2++)
        wsoff4[f2] = swz128((uint32_t)wn * 128 + (uint32_t)((wh * 32 + f2 * 8) << 1));

    // ldmatrix per-lane addressing: addr = row*128 + (kbyte ^ ((row&7)<<4))
    int m0w = (wid >> 2) * 64;
    int nw0 = (wid & 3) * 32;
    uint32_t aRowOff = (uint32_t)(m0w + (L & 15)) * 128;
    uint32_t bRowOff = (uint32_t)(nw0 + (L & 15)) * 128;
    uint32_t pat     = (uint32_t)(L & 7) << 4;
    uint32_t kb0     = (uint32_t)(L >> 4) << 4;

    float acc[4][4][4];
    #pragma unroll
    for (int i = 0; i < 4; i++)
        #pragma unroll
        for (int j = 0; j < 4; j++)
            #pragma unroll
            for (int q = 0; q < 4; q++) acc[i][j][q] = 0.0f;

    float4 aW[8];

    // ---- helpers as macros over locals ----
#define ISSUE_A(s_) do {                                                          \
        const char* _src = (const char*)(Aglob + (size_t)(blk0 + (s_)) * ABLK_BYTES) + t * 16; \
        uint32_t _dst = smb + ABUF((s_) % 3) + t * 16;                            \
        _Pragma("unroll")                                                         \
        for (int _i = 0; _i < 8; _i++) cpasync16(_dst + _i * 4096, _src + _i * 4096); \
    } while (0)

#define LOAD_W(s_) do {                                                           \
        int _koff = (s_) << 6;                                                    \
        _Pragma("unroll")                                                         \
        for (int _f = 0; _f < 8; _f++) {                                          \
            int _kk = _koff + wh * 32 + _f * 4;                                   \
            aW[_f] = (rvalid && _kk < klen) ? *(const float4*)(wrow + _kk)        \
                                            : make_float4(0.f, 0.f, 0.f, 0.f);    \
        }                                                                         \
    } while (0)

#define STORE_W(s_) do {                                                          \
        uint32_t _wb = WBUF((s_) & 1);                                            \
        _Pragma("unroll")                                                         \
        for (int _f2 = 0; _f2 < 4; _f2++) {                                       \
            float4 _a = aW[2 * _f2], _b = aW[2 * _f2 + 1];                        \
            uint32_t _h0 = bf2pack(_a.x, _a.y), _h1 = bf2pack(_a.z, _a.w);        \
            uint32_t _h2 = bf2pack(_b.x, _b.y), _h3 = bf2pack(_b.z, _b.w);        \
            float _r0 = _a.x - __uint_as_float(_h0 << 16);                        \
            float _r1 = _a.y - __uint_as_float(_h0 & 0xffff0000u);                \
            float _r2 = _a.z - __uint_as_float(_h1 << 16);                        \
            float _r3 = _a.w - __uint_as_float(_h1 & 0xffff0000u);                \
            float _r4 = _b.x - __uint_as_float(_h2 << 16);                        \
            float _r5 = _b.y - __uint_as_float(_h2 & 0xffff0000u);                \
            float _r6 = _b.z - __uint_as_float(_h3 << 16);                        \
            float _r7 = _b.w - __uint_as_float(_h3 & 0xffff0000u);                \
            uint32_t _l0 = bf2pack(_r0, _r1), _l1 = bf2pack(_r2, _r3);            \
            uint32_t _l2 = bf2pack(_r4, _r5), _l3 = bf2pack(_r6, _r7);            \
            *(uint4*)(sm + _wb + wsoff4[_f2])         = make_uint4(_h0, _h1, _h2, _h3); \
            *(uint4*)(sm + _wb + 16384 + wsoff4[_f2]) = make_uint4(_l0, _l1, _l2, _l3); \
        }                                                                         \
    } while (0)

    // ---- prolog ----
    ISSUE_A(0); CP_COMMIT();
    if (S > 1) ISSUE_A(1);
    CP_COMMIT();
    LOAD_W(0);
    STORE_W(0);
    if (S > 1) LOAD_W(1);
    CP_WAIT1();            // A0 landed (A1 may remain in flight)
    __syncthreads();

    // ---- main loop: ONE barrier per stage ----
    for (int s = 0; s < S; s++) {
        if (s + 1 < S) STORE_W(s + 1);          // into other W buffer
        if (s + 2 < S) ISSUE_A(s + 2);          // into third A buffer
        CP_COMMIT();
        if (s + 2 < S) LOAD_W(s + 2);           // LDG latency hidden by MMAs

        int lenS = min(64, klen - (s << 6));
        uint32_t aBase = smb + ABUF(s % 3) + aRowOff;
        uint32_t bBase = smb + WBUF(s & 1) + bRowOff;
        int nk16 = lenS >> 4;
        for (int ks = 0; ks < nk16; ks++) {
            uint32_t kx = (kb0 + (uint32_t)ks * 32) ^ pat;
            uint32_t Ah[4][4], Al[4][4], Bh[2][4], Bl[2][4];
            #pragma unroll
            for (int i = 0; i < 4; i++) {
                ldsm4(Ah[i], aBase + i * 2048 + kx);
                ldsm4(Al[i], aBase + 16384 + i * 2048 + kx);
            }
            #pragma unroll
            for (int p = 0; p < 2; p++) {
                ldsm4(Bh[p], bBase + p * 2048 + kx);
                ldsm4(Bl[p], bBase + 16384 + p * 2048 + kx);
            }
            #pragma unroll
            for (int i = 0; i < 4; i++)
                #pragma unroll
                for (int j = 0; j < 4; j++)
                    mma16816(acc[i][j], Ah[i], Bh[j >> 1][j & 1], Bh[j >> 1][(j & 1) + 2]);
            #pragma unroll
            for (int i = 0; i < 4; i++)
                #pragma unroll
                for (int j = 0; j < 4; j++)
                    mma16816(acc[i][j], Ah[i], Bl[j >> 1][j & 1], Bl[j >> 1][(j & 1) + 2]);
            #pragma unroll
            for (int i = 0; i < 4; i++)
                #pragma unroll
                for (int j = 0; j < 4; j++)
                    mma16816(acc[i][j], Al[i], Bh[j >> 1][j & 1], Bh[j >> 1][(j & 1) + 2]);
        }

        CP_WAIT1();         // A(s+1) landed
        __syncthreads();    // publish W(s+1) stores + A(s+1) + guard buffer reuse
    }

    // ---- epilogue: stage [n][m] tile in smem (stride 136), coalesced out ----
    {
        float* sp = (float*)sm;
        int row0 = m0w + (L >> 2);
        int col0 = nw0 + (L & 3) * 2;
        #pragma unroll
        for (int i = 0; i < 4; i++)
            #pragma unroll
            for (int j = 0; j < 4; j++) {
                int row = row0 + i * 16;
                int col = col0 + j * 8;
                float v0 = acc[i][j][0], v1 = acc[i][j][1];
                float v2 = acc[i][j][2], v3 = acc[i][j][3];
                if (MODE == 2) {
                    int na = n0 + col, nb = n0 + col + 1;
                    float ba = (na < N) ? bias[na] : 0.0f;
                    float bb = (nb < N) ? bias[nb] : 0.0f;
                    v0 = leaky(v0 + ba); v2 = leaky(v2 + ba);
                    v1 = leaky(v1 + bb); v3 = leaky(v3 + bb);
                }
                sp[col * EPI_STRIDE + row]           = v0;
                sp[(col + 1) * EPI_STRIDE + row]     = v1;
                sp[col * EPI_STRIDE + row + 8]       = v2;
                sp[(col + 1) * EPI_STRIDE + row + 8] = v3;
            }
        __syncthreads();
        #pragma unroll
        for (int it = 0; it < 16; it++) {
            int idx = it * 256 + t;
            int n  = idx >> 5;
            int f4 = idx & 31;
            float4 v = *(const float4*)(sp + n * EPI_STRIDE + f4 * 4);
            if (MODE == 1) {
                *(float4*)(out + ((size_t)blockIdx.y * NPAD + n0 + n) * 128 + f4 * 4) = v;
            } else {
                if (n0 + n < N)
                    *(float4*)(out + (size_t)(n0 + n) * 128 + f4 * 4) = v;
            }
        }
    }
#undef ISSUE_A
#undef LOAD_W
#undef STORE_W
}

// =====================================================================
// 3) FC1 reduction + bias + leaky -> z in A-format (bf16 hi/lo) g_zA
// =====================================================================
__global__ void reduce_z(const float* __restrict__ b1) {
    int n = blockIdx.x;
    int m = threadIdx.x;
    float s = b1[n];
    #pragma unroll
    for (int ks = 0; ks < KSPLIT; ks++)
        s += g_zpart[((size_t)ks * NPAD + n) * 128 + m];
    float val = leaky(s);
    __nv_bfloat16 hi = __float2bfloat16(val);
    __nv_bfloat16 lo = __float2bfloat16(val - __bfloat162float(hi));
    int blk = n >> 6;
    int kin = n & 63;
    uint32_t off = swz128((uint32_t)m * 128 + (uint32_t)(kin << 1));
    unsigned char* base = g_zA + (size_t)blk * ABLK_BYTES;
    *(__nv_bfloat16*)(base + off)         = hi;
    *(__nv_bfloat16*)(base + 16384 + off) = lo;
}

// =====================================================================
// 4) Decoder grouped deconv + sigmoid
// =====================================================================
__global__ void dec_conv(const float* __restrict__ dw,
                         const float* __restrict__ db,
                         float* __restrict__ out) {
    __shared__ float w_s[GB * 60];
    __shared__ float b_s[GB];
    __shared__ float dt_s[GB * 3 * 33];

    int g0 = blockIdx.x * GB;
    int ng = G_TOT - g0; if (ng > GB) ng = GB;
    int nk = ng * 3;
    int t  = threadIdx.x;

    for (int i = t; i < ng * 60; i += 256) w_s[i] = dw[(size_t)g0 * 60 + i];
    for (int i = t; i < ng;      i += 256) b_s[i] = db[g0 + i];
    __syncthreads();

    for (int bc = 0; bc < BATCH; bc += 32) {
        for (int e = t; e < nk * 32; e += 256) {
            int k = e >> 5, bb = e & 31;
            dt_s[k * 33 + bb] = g_dT[(size_t)(g0 * 3 + k) * 128 + bc + bb];
        }
        __syncthreads();
        for (int bb = 0; bb < 32; bb++) {
            int b = bc + bb;
            for (int idx = t; idx < ng * 20; idx += 256) {
                int g  = idx / 20;
                int kk = idx - g * 20;
                float v = fmaf(dt_s[(g * 3 + 0) * 33 + bb], w_s[g * 60 +      kk],
                          fmaf(dt_s[(g * 3 + 1) * 33 + bb], w_s[g * 60 + 20 + kk],
                          fmaf(dt_s[(g * 3 + 2) * 33 + bb], w_s[g * 60 + 40 + kk],
                               b_s[g])));
                out[(size_t)b * INLEN + (size_t)g0 * 20 + idx] =
                    1.0f / (1.0f + __expf(-v));
            }
        }
        __syncthreads();
    }
}

// =====================================================================
// launcher — graph-capturable, allocation-free
// =====================================================================
extern "C" void kernel_launch(void* const* d_in, const int* in_sizes, int n_in,
                              void* d_out, int out_size) {
    const float* x   = (const float*)d_in[0];
    const float* ew  = (const float*)d_in[1];
    const float* eb  = (const float*)d_in[2];
    const float* efw = (const float*)d_in[3];
    const float* efb = (const float*)d_in[4];
    const float* dfw = (const float*)d_in[5];
    const float* dfb = (const float*)d_in[6];
    const float* dw  = (const float*)d_in[7];
    const float* db  = (const float*)d_in[8];
    float* out = (float*)d_out;

    unsigned char *hA, *zA;
    float *zpart, *dT;
    cudaGetSymbolAddress((void**)&hA,    g_hA);
    cudaGetSymbolAddress((void**)&zA,    g_zA);
    cudaGetSymbolAddress((void**)&zpart, g_zpart);
    cudaGetSymbolAddress((void**)&dT,    g_dT);

    cudaFuncSetAttribute(gemm_mma<1>, cudaFuncAttributeMaxDynamicSharedMemorySize, SMEM_GEMM);
    cudaFuncSetAttribute(gemm_mma<2>, cudaFuncAttributeMaxDynamicSharedMemorySize, SMEM_GEMM);

    // 1) encoder grouped conv -> h (bf16 hi/lo, A-format)
    enc_conv<<<(G_TOT + GB - 1) / GB, 256>>>(x, ew, eb);
    // 2) FC1 mma GEMM (split-K) -> fp32 partials
    gemm_mma<1><<<dim3(16, KSPLIT), 256, SMEM_GEMM>>>(hA, efw, nullptr, zpart,
                                                      LAT, KDIM, KDIM, SPLIT_LEN);
    // 3) reduce + bias + leaky -> z (bf16 hi/lo, A-format)
    reduce_z<<<LAT, 128>>>(efb);
    // 4) FC2 mma GEMM, fused bias+leaky -> d^T (fp32)
    gemm_mma<2><<<dim3((KDIM + 127) / 128, 1), 256, SMEM_GEMM>>>(zA, dfw, dfb, dT,
                                                                 KDIM, LAT, LAT, 2048);
    // 5) decoder deconv + sigmoid -> out
    dec_conv<<<(G_TOT + GB - 1) / GB, 256>>>(dw, db, out);
}